// round 5
// baseline (speedup 1.0000x reference)
#include <cuda_runtime.h>
#include <cuda_bf16.h>
#include <cstdint>

#define IN_F   4096
#define OUT_F  4096
#define NTOK   16384
#define BW     8
#define KW     17           // 2*BW+1
#define NO     8            // outputs per thread
#define WARPS  4            // warps per block (128 threads)
#define GY     256          // token groups (grid.y) -> 64 tokens per block
#define WIN_F  (32*NO + 2*BW)   // 272 floats per warp window
#define WIN4   (WIN_F/4)        // 68 chunks
#define SBUF4  76               // padded chunks per buffer
#define NBUF   5
#define PDIST  3
#define ROWS_W 256              // band rows staged per chunk (one warp's outputs)

// padded smem float index: +4 floats of pad after every 32 floats
__device__ __forceinline__ int padidx(int j) { return j + ((j >> 5) << 2); }

__device__ __forceinline__ void cp16(uint32_t dst_smem, const float* src) {
    asm volatile("cp.async.cg.shared.global [%0], [%1], 16;\n"
                 :: "r"(dst_smem), "l"(src) : "memory");
}
__device__ __forceinline__ void cp_commit() {
    asm volatile("cp.async.commit_group;\n" ::: "memory");
}
__device__ __forceinline__ void cp_waitP() {
    asm volatile("cp.async.wait_group %0;\n" :: "n"(PDIST) : "memory");
}

// warp covers 32*NO = 256 consecutive outputs; block covers 1024; grid.x = 4.
__global__ __launch_bounds__(128, 2) void band_linear_kernel(
    const float* __restrict__ x,
    const float* __restrict__ w,
    const float* __restrict__ bias,
    float* __restrict__ out)
{
    __shared__ float4 sm[WARPS][NBUF][SBUF4];   // x pipeline: 24320 B
    __shared__ float  smw[ROWS_W * KW];         // weight stage: 17408 B

    const int warp = threadIdx.x >> 5;
    const int lane = threadIdx.x & 31;
    const int wbase  = (blockIdx.x * WARPS + warp) * (32 * NO);
    const int o_base = wbase + lane * NO;
    const int win0   = wbase - BW;               // multiple of 4

    // ---- coalesced band-weight staging: 4 chunks of 256 rows x 17 cols ----
    float wr[NO][KW];
    float br[NO];
#pragma unroll 1
    for (int cc = 0; cc < WARPS; ++cc) {
        const int row0 = blockIdx.x * (WARPS * ROWS_W) + cc * ROWS_W;
#pragma unroll 1
        for (int e = threadIdx.x; e < ROWS_W * KW; e += 128) {
            const int r = e / KW;
            const int k = e - r * KW;
            const int o = row0 + r;
            const int col = o - BW + k;
            smw[e] = (col >= 0 && col < IN_F) ? w[(long)o * IN_F + col] : 0.0f;
        }
        __syncthreads();
        if (warp == cc) {
#pragma unroll
            for (int oo = 0; oo < NO; ++oo)
#pragma unroll
                for (int k = 0; k < KW; ++k)
                    wr[oo][k] = smw[(lane * NO + oo) * KW + k];
        }
        __syncthreads();
    }
#pragma unroll
    for (int oo = 0; oo < NO; ++oo)
        br[oo] = bias[o_base + oo];

    // ---- x staging chunk assignment: 68 chunks over 32 lanes ----
    const int  c0 = lane;
    const int  c1 = lane + 32;
    const bool extra = (lane < WIN4 - 64);   // lanes 0..3 take chunks 64..67
    const int  c2 = lane + 64;

    int s0 = win0 + 4 * c0;
    s0 = s0 < 0 ? 0 : (s0 > IN_F - 4 ? IN_F - 4 : s0);
    int s1 = win0 + 4 * c1;
    s1 = s1 < 0 ? 0 : (s1 > IN_F - 4 ? IN_F - 4 : s1);
    int s2 = win0 + 4 * c2;
    s2 = s2 < 0 ? 0 : (s2 > IN_F - 4 ? IN_F - 4 : s2);
    // clamped chunks pair only with zero weights -> harmless.

    const uint32_t wsm  = (uint32_t)__cvta_generic_to_shared(&sm[warp][0][0]);
    const uint32_t off0 = (uint32_t)((c0 + (c0 >> 3)) * 16);
    const uint32_t off1 = (uint32_t)((c1 + (c1 >> 3)) * 16);
    const uint32_t off2 = (uint32_t)((c2 + (c2 >> 3)) * 16);

    const int n0 = blockIdx.y;

    // ---- pipeline prologue: stage tokens n0 .. n0+2*GY into buffers 0..2 ----
#pragma unroll
    for (int p = 0; p < PDIST; ++p) {
        const int tn = n0 + p * GY;
        if (tn < NTOK) {
            const float* xrow = x + (long)tn * IN_F;
            const uint32_t b = wsm + (uint32_t)(p * SBUF4 * 16);
            cp16(b + off0, xrow + s0);
            cp16(b + off1, xrow + s1);
            if (extra) cp16(b + off2, xrow + s2);
        }
        cp_commit();
    }

    int buf = 0;
    int pbuf = PDIST;
    for (int n = n0; n < NTOK; n += GY) {
        // ---- stage token n + PDIST*GY ----
        const int pn = n + PDIST * GY;
        if (pn < NTOK) {
            const float* xrow = x + (long)pn * IN_F;
            const uint32_t b = wsm + (uint32_t)(pbuf * SBUF4 * 16);
            cp16(b + off0, xrow + s0);
            cp16(b + off1, xrow + s1);
            if (extra) cp16(b + off2, xrow + s2);
        }
        cp_commit();

        cp_waitP();
        __syncwarp();

        // ---- compute token n: 24-float window via 6 conflict-free LDS.128 ----
        const float* swp = reinterpret_cast<const float*>(&sm[warp][buf][0]);
        float xr[NO + 2 * BW];   // 24
#pragma unroll
        for (int c = 0; c < 6; ++c) {
            const int j0 = lane * NO + 4 * c;
            const float4 v = *reinterpret_cast<const float4*>(swp + padidx(j0));
            xr[4 * c + 0] = v.x;
            xr[4 * c + 1] = v.y;
            xr[4 * c + 2] = v.z;
            xr[4 * c + 3] = v.w;
        }

        float acc[NO];
#pragma unroll
        for (int oo = 0; oo < NO; ++oo) {
            float a = br[oo];
#pragma unroll
            for (int k = 0; k < KW; ++k)
                a = fmaf(wr[oo][k], xr[oo + k], a);
            acc[oo] = a;
        }

        float* orow = out + (long)n * OUT_F + o_base;
        float4 o4a, o4b;
        o4a.x = acc[0]; o4a.y = acc[1]; o4a.z = acc[2]; o4a.w = acc[3];
        o4b.x = acc[4]; o4b.y = acc[5]; o4b.z = acc[6]; o4b.w = acc[7];
        *reinterpret_cast<float4*>(orow)     = o4a;
        *reinterpret_cast<float4*>(orow + 4) = o4b;

        buf  = (buf  + 1 == NBUF) ? 0 : buf  + 1;
        pbuf = (pbuf + 1 == NBUF) ? 0 : pbuf + 1;
    }
}

extern "C" void kernel_launch(void* const* d_in, const int* in_sizes, int n_in,
                              void* d_out, int out_size)
{
    const float* x    = (const float*)d_in[0];   // [NTOK, IN_F]
    const float* w    = (const float*)d_in[1];   // [OUT_F, IN_F]
    const float* bias = (const float*)d_in[2];   // [OUT_F]
    float* out = (float*)d_out;

    dim3 grid(OUT_F / (WARPS * 32 * NO), GY);    // (4, 256)
    dim3 block(WARPS * 32);                      // 128
    band_linear_kernel<<<grid, block>>>(x, w, bias, out);
}

// round 6
// speedup vs baseline: 1.2894x; 1.2894x over previous
#include <cuda_runtime.h>
#include <cuda_bf16.h>
#include <cstdint>

#define IN_F   4096
#define OUT_F  4096
#define NTOK   16384
#define BW     8
#define KW     17          // 2*BW+1
#define NO     4           // outputs per thread
#define WARPS  8           // warps per block (256 threads)
#define GY     512         // token groups (grid.y)
#define WIN4   36          // float4 chunks per warp window (144 floats)
#define SBUF4  40          // padded chunks per buffer
#define NBUF   5
#define PDIST  3
#define WCH    256         // weight rows staged per chunk (2 warps' outputs)

__device__ __forceinline__ void cp16(uint32_t dst_smem, const float* src) {
    asm volatile("cp.async.cg.shared.global [%0], [%1], 16;\n"
                 :: "r"(dst_smem), "l"(src) : "memory");
}
__device__ __forceinline__ void cp_commit() {
    asm volatile("cp.async.commit_group;\n" ::: "memory");
}
__device__ __forceinline__ void cp_waitP() {
    asm volatile("cp.async.wait_group %0;\n" :: "n"(PDIST) : "memory");
}

// warp covers 32*NO = 128 consecutive outputs; block covers 1024; grid.x = 4.
__global__ __launch_bounds__(256, 2) void band_linear_kernel(
    const float* __restrict__ x,
    const float* __restrict__ w,
    const float* __restrict__ bias,
    float* __restrict__ out)
{
    __shared__ float4 sm[WARPS][NBUF][SBUF4];   // x pipeline: 25600 B
    __shared__ float  smw[WCH * KW];            // weight stage: 17408 B

    const int warp = threadIdx.x >> 5;
    const int lane = threadIdx.x & 31;
    const int wbase  = (blockIdx.x * WARPS + warp) * (32 * NO);
    const int o_base = wbase + lane * NO;
    const int win0   = wbase - BW;               // multiple of 4

    // ---- coalesced band-weight staging: 4 chunks of 256 rows x 17 cols ----
    // Chunk cc stages rows for warps 2cc and 2cc+1; all 256 threads cooperate
    // with a flat copy (consecutive threads -> consecutive columns).
    float wr[NO][KW];
    float br[NO];
#pragma unroll 1
    for (int cc = 0; cc < WARPS / 2; ++cc) {
        const int row0 = blockIdx.x * (WARPS * 32 * NO) + cc * WCH;
#pragma unroll 1
        for (int e = threadIdx.x; e < WCH * KW; e += 256) {
            const int r = e / KW;
            const int k = e - r * KW;
            const int o = row0 + r;
            const int col = o - BW + k;
            smw[e] = (col >= 0 && col < IN_F) ? w[(long)o * IN_F + col] : 0.0f;
        }
        __syncthreads();
        if ((warp >> 1) == cc) {
            const int rloc = (warp & 1) * 128 + lane * NO;
#pragma unroll
            for (int oo = 0; oo < NO; ++oo)
#pragma unroll
                for (int k = 0; k < KW; ++k)
                    wr[oo][k] = smw[(rloc + oo) * KW + k];
        }
        __syncthreads();
    }
#pragma unroll
    for (int oo = 0; oo < NO; ++oo)
        br[oo] = bias[o_base + oo];

    // ---- x staging chunk assignment (coalesced, 36 chunks over 32 lanes) ----
    const int  c0    = lane;
    const bool extra = (lane < WIN4 - 32);   // lanes 0..3 take chunks 32..35
    const int  c1    = 32 + lane;

    int s0 = win0 + 4 * c0;
    s0 = s0 < 0 ? 0 : (s0 > IN_F - 4 ? IN_F - 4 : s0);
    int s1 = win0 + 4 * c1;
    s1 = s1 < 0 ? 0 : (s1 > IN_F - 4 ? IN_F - 4 : s1);
    // clamped chunks pair only with zero weights -> harmless.

    const uint32_t wsm  = (uint32_t)__cvta_generic_to_shared(&sm[warp][0][0]);
    const uint32_t off0 = (uint32_t)(c0 * 16);
    const uint32_t off1 = (uint32_t)(c1 * 16);

    const int n0 = blockIdx.y;

    // ---- prologue: stage tokens n0 .. n0+2*GY into buffers 0..2 ----
#pragma unroll
    for (int p = 0; p < PDIST; ++p) {
        const int tn = n0 + p * GY;
        if (tn < NTOK) {
            const float* xrow = x + (long)tn * IN_F;
            const uint32_t b = wsm + (uint32_t)(p * SBUF4 * 16);
            cp16(b + off0, xrow + s0);
            if (extra) cp16(b + off1, xrow + s1);
        }
        cp_commit();
    }

    int buf = 0;
    int pbuf = PDIST;
    for (int n = n0; n < NTOK; n += GY) {
        // ---- stage token n + PDIST*GY (depth-3 prefetch) ----
        const int pn = n + PDIST * GY;
        if (pn < NTOK) {
            const float* xrow = x + (long)pn * IN_F;
            const uint32_t b = wsm + (uint32_t)(pbuf * SBUF4 * 16);
            cp16(b + off0, xrow + s0);
            if (extra) cp16(b + off1, xrow + s1);
        }
        cp_commit();

        cp_waitP();
        __syncwarp();

        // ---- compute token n from smem (conflict-free LDS.128) ----
        const float* swp = reinterpret_cast<const float*>(&sm[warp][buf][0]);
        float xr[NO + 2 * BW];  // 20
#pragma unroll
        for (int c = 0; c < 5; ++c) {
            const float4 v = *reinterpret_cast<const float4*>(swp + lane * NO + 4 * c);
            xr[4 * c + 0] = v.x;
            xr[4 * c + 1] = v.y;
            xr[4 * c + 2] = v.z;
            xr[4 * c + 3] = v.w;
        }

        float acc[NO];
#pragma unroll
        for (int oo = 0; oo < NO; ++oo) {
            float a = br[oo];
#pragma unroll
            for (int k = 0; k < KW; ++k)
                a = fmaf(wr[oo][k], xr[oo + k], a);
            acc[oo] = a;
        }

        float4 o4;
        o4.x = acc[0]; o4.y = acc[1]; o4.z = acc[2]; o4.w = acc[3];
        *reinterpret_cast<float4*>(out + (long)n * OUT_F + o_base) = o4;

        buf  = (buf  + 1 == NBUF) ? 0 : buf  + 1;
        pbuf = (pbuf + 1 == NBUF) ? 0 : pbuf + 1;
    }
}

extern "C" void kernel_launch(void* const* d_in, const int* in_sizes, int n_in,
                              void* d_out, int out_size)
{
    const float* x    = (const float*)d_in[0];   // [NTOK, IN_F]
    const float* w    = (const float*)d_in[1];   // [OUT_F, IN_F]
    const float* bias = (const float*)d_in[2];   // [OUT_F]
    float* out = (float*)d_out;

    dim3 grid(OUT_F / (WARPS * 32 * NO), GY);    // (4, 512)
    dim3 block(WARPS * 32);                      // 256
    band_linear_kernel<<<grid, block>>>(x, w, bias, out);
}

// round 7
// speedup vs baseline: 2.7749x; 2.1520x over previous
#include <cuda_runtime.h>
#include <cuda_bf16.h>
#include <cstdint>

#define IN_F   4096
#define OUT_F  4096
#define NTOK   16384
#define BW     8
#define KW     17          // 2*BW+1
#define NO     4           // outputs per thread
#define WARPS  8           // warps per block (256 threads)
#define GY     512         // token groups (grid.y)
#define WIN4   36          // float4 chunks per warp window (144 floats)
#define SBUF4  40          // padded chunks per buffer
#define NBUF   5
#define PDIST  3
#define BROWS  (WARPS * 32 * NO)       // 1024 band rows per block
#define WST_F  (BROWS * KW)            // 17408 staged weight floats
#define PIPE_B (WARPS * NBUF * SBUF4 * 16)   // 25600 B
#define SMEM_B (PIPE_B + WST_F * 4)          // 95232 B dynamic smem

__device__ __forceinline__ void cp16(uint32_t dst_smem, const float* src) {
    asm volatile("cp.async.cg.shared.global [%0], [%1], 16;\n"
                 :: "r"(dst_smem), "l"(src) : "memory");
}
__device__ __forceinline__ void cp4(uint32_t dst_smem, const float* src) {
    asm volatile("cp.async.ca.shared.global [%0], [%1], 4;\n"
                 :: "r"(dst_smem), "l"(src) : "memory");
}
__device__ __forceinline__ void cp_commit() {
    asm volatile("cp.async.commit_group;\n" ::: "memory");
}
__device__ __forceinline__ void cp_waitP() {
    asm volatile("cp.async.wait_group %0;\n" :: "n"(PDIST) : "memory");
}

// warp covers 32*NO = 128 consecutive outputs; block covers 1024; grid.x = 4.
__global__ __launch_bounds__(256, 2) void band_linear_kernel(
    const float* __restrict__ x,
    const float* __restrict__ w,
    const float* __restrict__ bias,
    float* __restrict__ out)
{
    extern __shared__ char dsm[];
    float4* smp = reinterpret_cast<float4*>(dsm);            // x pipeline
    float*  smw = reinterpret_cast<float*>(dsm + PIPE_B);    // weight stage

    const int warp = threadIdx.x >> 5;
    const int lane = threadIdx.x & 31;
    const int wbase  = (blockIdx.x * WARPS + warp) * (32 * NO);
    const int o_base = wbase + lane * NO;
    const int win0   = wbase - BW;               // multiple of 4

    // ---- async coalesced weight staging: 1024 rows x 17 taps, one group ----
    {
        const int row0 = blockIdx.x * BROWS;
        const uint32_t smw_a = (uint32_t)__cvta_generic_to_shared(smw);
#pragma unroll
        for (int i = 0; i < WST_F / 256; ++i) {              // 68 cp.async each
            const int e = threadIdx.x + i * 256;
            const int r = e / KW;
            const int k = e - r * KW;
            const int o = row0 + r;
            int col = o - BW + k;
            col = col < 0 ? 0 : (col >= IN_F ? IN_F - 1 : col);  // clamp; zeroed later
            cp4(smw_a + (uint32_t)(e * 4), w + (long)o * IN_F + col);
        }
        cp_commit();                                         // group W (oldest)
    }

    // ---- x staging chunk assignment (coalesced, 36 chunks over 32 lanes) ----
    const int  c0    = lane;
    const bool extra = (lane < WIN4 - 32);   // lanes 0..3 take chunks 32..35
    const int  c1    = 32 + lane;

    int s0 = win0 + 4 * c0;
    s0 = s0 < 0 ? 0 : (s0 > IN_F - 4 ? IN_F - 4 : s0);
    int s1 = win0 + 4 * c1;
    s1 = s1 < 0 ? 0 : (s1 > IN_F - 4 ? IN_F - 4 : s1);
    // clamped chunks pair only with zero weights -> harmless.

    const uint32_t wsm  = (uint32_t)__cvta_generic_to_shared(smp + (size_t)warp * NBUF * SBUF4);
    const uint32_t off0 = (uint32_t)(c0 * 16);
    const uint32_t off1 = (uint32_t)(c1 * 16);

    const int n0 = blockIdx.y;

    // ---- x prologue: stage tokens n0 .. n0+2*GY into buffers 0..2 ----
#pragma unroll
    for (int p = 0; p < PDIST; ++p) {
        const int tn = n0 + p * GY;
        if (tn < NTOK) {
            const float* xrow = x + (long)tn * IN_F;
            const uint32_t b = wsm + (uint32_t)(p * SBUF4 * 16);
            cp16(b + off0, xrow + s0);
            if (extra) cp16(b + off1, xrow + s1);
        }
        cp_commit();
    }

    // ---- wait for weight group (oldest of 4), then copy to registers ----
    asm volatile("cp.async.wait_group %0;\n" :: "n"(PDIST) : "memory");
    __syncthreads();

    float wr[NO][KW];
    float br[NO];
    {
        const int rloc = warp * 128 + lane * NO;
#pragma unroll
        for (int oo = 0; oo < NO; ++oo) {
            const int o = o_base + oo;
            br[oo] = bias[o];
#pragma unroll
            for (int k = 0; k < KW; ++k) {
                const int col = o - BW + k;
                const float v = smw[(rloc + oo) * KW + k];
                wr[oo][k] = (col >= 0 && col < IN_F) ? v : 0.0f;
            }
        }
    }

    int buf = 0;
    int pbuf = PDIST;
    for (int n = n0; n < NTOK; n += GY) {
        // ---- stage token n + PDIST*GY (depth-3 prefetch) ----
        const int pn = n + PDIST * GY;
        if (pn < NTOK) {
            const float* xrow = x + (long)pn * IN_F;
            const uint32_t b = wsm + (uint32_t)(pbuf * SBUF4 * 16);
            cp16(b + off0, xrow + s0);
            if (extra) cp16(b + off1, xrow + s1);
        }
        cp_commit();

        cp_waitP();
        __syncwarp();

        // ---- compute token n from smem (conflict-free LDS.128) ----
        const float* swp = reinterpret_cast<const float*>(smp + (size_t)warp * NBUF * SBUF4
                                                              + (size_t)buf * SBUF4);
        float xr[NO + 2 * BW];  // 20
#pragma unroll
        for (int c = 0; c < 5; ++c) {
            const float4 v = *reinterpret_cast<const float4*>(swp + lane * NO + 4 * c);
            xr[4 * c + 0] = v.x;
            xr[4 * c + 1] = v.y;
            xr[4 * c + 2] = v.z;
            xr[4 * c + 3] = v.w;
        }

        float acc[NO];
#pragma unroll
        for (int oo = 0; oo < NO; ++oo) {
            float a = br[oo];
#pragma unroll
            for (int k = 0; k < KW; ++k)
                a = fmaf(wr[oo][k], xr[oo + k], a);
            acc[oo] = a;
        }

        float4 o4;
        o4.x = acc[0]; o4.y = acc[1]; o4.z = acc[2]; o4.w = acc[3];
        *reinterpret_cast<float4*>(out + (long)n * OUT_F + o_base) = o4;

        buf  = (buf  + 1 == NBUF) ? 0 : buf  + 1;
        pbuf = (pbuf + 1 == NBUF) ? 0 : pbuf + 1;
    }
}

extern "C" void kernel_launch(void* const* d_in, const int* in_sizes, int n_in,
                              void* d_out, int out_size)
{
    const float* x    = (const float*)d_in[0];   // [NTOK, IN_F]
    const float* w    = (const float*)d_in[1];   // [OUT_F, IN_F]
    const float* bias = (const float*)d_in[2];   // [OUT_F]
    float* out = (float*)d_out;

    cudaFuncSetAttribute(band_linear_kernel,
                         cudaFuncAttributeMaxDynamicSharedMemorySize, SMEM_B);

    dim3 grid(OUT_F / (WARPS * 32 * NO), GY);    // (4, 512)
    dim3 block(WARPS * 32);                      // 256
    band_linear_kernel<<<grid, block, SMEM_B>>>(x, w, bias, out);
}

// round 8
// speedup vs baseline: 3.2869x; 1.1845x over previous
#include <cuda_runtime.h>
#include <cuda_bf16.h>
#include <cstdint>

#define IN_F   4096
#define OUT_F  4096
#define NTOK   16384
#define BW     8
#define KW     17          // 2*BW+1
#define NO     4           // outputs per thread
#define WARPS  8           // warps per block (256 threads)
#define GY     256         // token stride / grid.y  -> 64 tokens per block
#define WIN4   36          // float4 chunks per warp window (144 floats)
#define SBUF4  40          // chunks per buffer
#define NBUF   8           // power of two (unroll-2 friendly)
#define PDIST  6           // prefetch distance (tokens ahead)
#define BROWS  (WARPS * 32 * NO)           // 1024 band rows per block
#define WST_F  (BROWS * KW)                // 17408 staged weight floats
#define PIPE_B (WARPS * NBUF * SBUF4 * 16) // 40960 B
#define WST_B  (WST_F * 4)                 // 69632 B
#define SMEM_B (WST_B > PIPE_B ? WST_B : PIPE_B)   // union: 69632 B

__device__ __forceinline__ void cp16(uint32_t dst_smem, const float* src) {
    asm volatile("cp.async.cg.shared.global [%0], [%1], 16;\n"
                 :: "r"(dst_smem), "l"(src) : "memory");
}
__device__ __forceinline__ void cp4(uint32_t dst_smem, const float* src) {
    asm volatile("cp.async.ca.shared.global [%0], [%1], 4;\n"
                 :: "r"(dst_smem), "l"(src) : "memory");
}
__device__ __forceinline__ void cp_commit() {
    asm volatile("cp.async.commit_group;\n" ::: "memory");
}

// warp covers 32*NO = 128 consecutive outputs; block covers 1024; grid.x = 4.
__global__ __launch_bounds__(256, 2) void band_linear_kernel(
    const float* __restrict__ x,
    const float* __restrict__ w,
    const float* __restrict__ bias,
    float* __restrict__ out)
{
    extern __shared__ char dsm[];
    float4* smp = reinterpret_cast<float4*>(dsm);         // x pipeline (after weights consumed)
    float*  smw = reinterpret_cast<float*>(dsm);          // weight stage (union)

    const int warp = threadIdx.x >> 5;
    const int lane = threadIdx.x & 31;
    const int wbase  = (blockIdx.x * WARPS + warp) * (32 * NO);
    const int o_base = wbase + lane * NO;
    const int win0   = wbase - BW;               // multiple of 4

    // ---- async coalesced weight staging: 1024 rows x 17 taps, one group ----
    {
        const int row0 = blockIdx.x * BROWS;
        const uint32_t smw_a = (uint32_t)__cvta_generic_to_shared(smw);
#pragma unroll
        for (int i = 0; i < WST_F / 256; ++i) {              // 68 cp.async each
            const int e = threadIdx.x + i * 256;
            const int r = e / KW;
            const int k = e - r * KW;
            const int o = row0 + r;
            int col = o - BW + k;
            col = col < 0 ? 0 : (col >= IN_F ? IN_F - 1 : col);  // clamp; zeroed later
            cp4(smw_a + (uint32_t)(e * 4), w + (long)o * IN_F + col);
        }
        cp_commit();
    }
    asm volatile("cp.async.wait_group 0;\n" ::: "memory");
    __syncthreads();

    // ---- copy weights smem -> registers, then smem is recycled for x ----
    float wr[NO][KW];
    float br[NO];
    {
        const int rloc = warp * 128 + lane * NO;
#pragma unroll
        for (int oo = 0; oo < NO; ++oo) {
            const int o = o_base + oo;
            br[oo] = bias[o];
#pragma unroll
            for (int k = 0; k < KW; ++k) {
                const int col = o - BW + k;
                const float v = smw[(rloc + oo) * KW + k];
                wr[oo][k] = (col >= 0 && col < IN_F) ? v : 0.0f;
            }
        }
    }
    __syncthreads();   // all reads of smw done before pipeline overwrites it

    // ---- x staging chunk assignment (coalesced, 36 chunks over 32 lanes) ----
    const int  c0    = lane;
    const bool extra = (lane < WIN4 - 32);   // lanes 0..3 take chunks 32..35
    const int  c1    = 32 + lane;

    int s0 = win0 + 4 * c0;
    s0 = s0 < 0 ? 0 : (s0 > IN_F - 4 ? IN_F - 4 : s0);
    int s1 = win0 + 4 * c1;
    s1 = s1 < 0 ? 0 : (s1 > IN_F - 4 ? IN_F - 4 : s1);
    // clamped chunks pair only with zero weights -> harmless.

    const uint32_t wsm  = (uint32_t)__cvta_generic_to_shared(smp + (size_t)warp * NBUF * SBUF4);
    const uint32_t off0 = (uint32_t)(c0 * 16);
    const uint32_t off1 = (uint32_t)(c1 * 16);

    const int n0 = blockIdx.y;

    // ---- prologue: stage tokens n0 .. n0+5*GY into buffers 0..5 ----
#pragma unroll
    for (int p = 0; p < PDIST; ++p) {
        const int tn = n0 + p * GY;        // always < NTOK (n0<256, p<6)
        const float* xrow = x + (long)tn * IN_F;
        const uint32_t b = wsm + (uint32_t)(p * SBUF4 * 16);
        cp16(b + off0, xrow + s0);
        if (extra) cp16(b + off1, xrow + s1);
        cp_commit();
    }

    int buf  = 0;
    int pbuf = PDIST;
    for (int n = n0; n < NTOK; n += 2 * GY) {
        // ---- stage tokens n+6*GY and n+7*GY (two groups) ----
        {
            const int pnA = n + PDIST * GY;
            if (pnA < NTOK) {
                const float* xrow = x + (long)pnA * IN_F;
                const uint32_t b = wsm + (uint32_t)(pbuf * SBUF4 * 16);
                cp16(b + off0, xrow + s0);
                if (extra) cp16(b + off1, xrow + s1);
            }
            cp_commit();
            const int pnB = n + (PDIST + 1) * GY;
            if (pnB < NTOK) {
                const float* xrow = x + (long)pnB * IN_F;
                const uint32_t b = wsm + (uint32_t)(((pbuf + 1) & (NBUF - 1)) * SBUF4 * 16);
                cp16(b + off0, xrow + s0);
                if (extra) cp16(b + off1, xrow + s1);
            }
            cp_commit();
        }

        // ---- wait: <= PDIST groups pending => bufs (buf, buf+1) complete ----
        asm volatile("cp.async.wait_group %0;\n" :: "n"(PDIST) : "memory");
        __syncwarp();

        const float* wb = reinterpret_cast<const float*>(smp + (size_t)warp * NBUF * SBUF4);

        // ================= token A (buffer buf) =================
        {
            const float* swp = wb + (size_t)buf * SBUF4 * 4;
            float xr[NO + 2 * BW];
#pragma unroll
            for (int c = 0; c < 5; ++c) {
                const float4 v = *reinterpret_cast<const float4*>(swp + lane * NO + 4 * c);
                xr[4 * c + 0] = v.x;
                xr[4 * c + 1] = v.y;
                xr[4 * c + 2] = v.z;
                xr[4 * c + 3] = v.w;
            }
            float acc[NO];
#pragma unroll
            for (int oo = 0; oo < NO; ++oo) {
                float a = br[oo];
#pragma unroll
                for (int k = 0; k < KW; ++k)
                    a = fmaf(wr[oo][k], xr[oo + k], a);
                acc[oo] = a;
            }
            float4 o4;
            o4.x = acc[0]; o4.y = acc[1]; o4.z = acc[2]; o4.w = acc[3];
            *reinterpret_cast<float4*>(out + (long)n * OUT_F + o_base) = o4;
        }

        // ================= token B (buffer buf+1) =================
        {
            const int nB = n + GY;           // always < NTOK (n0 < GY)
            const float* swp = wb + (size_t)((buf + 1) & (NBUF - 1)) * SBUF4 * 4;
            float xr[NO + 2 * BW];
#pragma unroll
            for (int c = 0; c < 5; ++c) {
                const float4 v = *reinterpret_cast<const float4*>(swp + lane * NO + 4 * c);
                xr[4 * c + 0] = v.x;
                xr[4 * c + 1] = v.y;
                xr[4 * c + 2] = v.z;
                xr[4 * c + 3] = v.w;
            }
            float acc[NO];
#pragma unroll
            for (int oo = 0; oo < NO; ++oo) {
                float a = br[oo];
#pragma unroll
                for (int k = 0; k < KW; ++k)
                    a = fmaf(wr[oo][k], xr[oo + k], a);
                acc[oo] = a;
            }
            float4 o4;
            o4.x = acc[0]; o4.y = acc[1]; o4.z = acc[2]; o4.w = acc[3];
            *reinterpret_cast<float4*>(out + (long)nB * OUT_F + o_base) = o4;
        }

        buf  = (buf  + 2) & (NBUF - 1);
        pbuf = (pbuf + 2) & (NBUF - 1);
    }
}

extern "C" void kernel_launch(void* const* d_in, const int* in_sizes, int n_in,
                              void* d_out, int out_size)
{
    const float* x    = (const float*)d_in[0];   // [NTOK, IN_F]
    const float* w    = (const float*)d_in[1];   // [OUT_F, IN_F]
    const float* bias = (const float*)d_in[2];   // [OUT_F]
    float* out = (float*)d_out;

    cudaFuncSetAttribute(band_linear_kernel,
                         cudaFuncAttributeMaxDynamicSharedMemorySize, SMEM_B);

    dim3 grid(OUT_F / (WARPS * 32 * NO), GY);    // (4, 256)
    dim3 block(WARPS * 32);                      // 256
    band_linear_kernel<<<grid, block, SMEM_B>>>(x, w, bias, out);
}